// round 7
// baseline (speedup 1.0000x reference)
#include <cuda_runtime.h>
#include <cstdint>

#define BB 2
#define CC 256
#define HH 128
#define WW 128
#define H2 256
#define W2 256
#define PLANE (HH * WW)

#define CPG 64        // channels per carafe block -> 512 blocks = 1 wave
#define STAGE 4       // channels per pipeline stage
#define NS (CPG / STAGE)
#define NBUF 2
#define PRSTR 132     // smem row stride in float2 PAIRS (col c -> pair index c+2)
#define CHP (4 * PRSTR)   // pairs per channel tile (4 rows)

#define MG 16         // mean partial groups

// scratch (no allocations allowed)
__device__ float g_part[BB * MG * PLANE];
__device__ float g_mean[BB * PLANE];
__device__ float g_kern[BB * 9 * H2 * W2];

typedef unsigned long long ull;

// ---------------------------------------------------------------------------
// Kernel A1: partial channel sums (CC/MG channels per slice, float4 pixels)
// ---------------------------------------------------------------------------
__global__ void mean1_kernel(const float* __restrict__ x) {
    int t  = threadIdx.x;
    int p4 = blockIdx.x * 256 + t;
    int cg = blockIdx.y;
    int b  = blockIdx.z;
    const float4* xp = (const float4*)x
                     + (size_t)(b * CC + cg * (CC / MG)) * (PLANE / 4) + p4;
    float4 s = make_float4(0.f, 0.f, 0.f, 0.f);
#pragma unroll
    for (int c = 0; c < CC / MG; ++c) {
        float4 v = xp[(size_t)c * (PLANE / 4)];
        s.x += v.x; s.y += v.y; s.z += v.z; s.w += v.w;
    }
    ((float4*)g_part)[((size_t)(b * MG + cg)) * (PLANE / 4) + p4] = s;
}

// ---------------------------------------------------------------------------
// Kernel A2: combine partials -> mean
// ---------------------------------------------------------------------------
__global__ void mean2_kernel() {
    int idx = blockIdx.x * 256 + threadIdx.x;
    int b   = idx / (PLANE / 4);
    int p4  = idx % (PLANE / 4);
    float4 s = make_float4(0.f, 0.f, 0.f, 0.f);
#pragma unroll
    for (int g = 0; g < MG; ++g) {
        float4 v = ((const float4*)g_part)[((size_t)(b * MG + g)) * (PLANE / 4) + p4];
        s.x += v.x; s.y += v.y; s.z += v.z; s.w += v.w;
    }
    const float sc = 1.0f / CC;
    s.x *= sc; s.y *= sc; s.z *= sc; s.w *= sc;
    ((float4*)g_mean)[(size_t)b * (PLANE / 4) + p4] = s;
}

// ---------------------------------------------------------------------------
// Kernel B: parity-folded 3x3 conv (== 5x5 on nearest-up2) + gating + softmax
// ---------------------------------------------------------------------------
__device__ __forceinline__ float fast_tanh(float x) {
    float e = __expf(2.0f * x);
    return __fdividef(e - 1.0f, e + 1.0f);
}

__global__ void kern_kernel(const float* __restrict__ Woff,
                            const float* __restrict__ boff) {
    __shared__ float KW[2][2][2][9];   // [ch][pi][pj][di*3+dj]
    __shared__ float sb[2];
    int t = threadIdx.x;
    if (t < 72) {
        int ch  = t / 36, rem = t % 36;
        int pi  = rem / 18, pj = (rem / 9) & 1, k = rem % 9;
        int di  = k / 3, dj = k % 3;
        int us  = pi == 0 ? di * 2 : (di == 0 ? 0 : di * 2 - 1);
        int uc  = pi == 0 ? (di < 2 ? 2 : 1) : (di == 0 ? 1 : 2);
        int vs  = pj == 0 ? dj * 2 : (dj == 0 ? 0 : dj * 2 - 1);
        int vc  = pj == 0 ? (dj < 2 ? 2 : 1) : (dj == 0 ? 1 : 2);
        float s = 0.f;
        for (int u = 0; u < uc; ++u)
            for (int v = 0; v < vc; ++v)
                s += Woff[ch * 25 + (us + u) * 5 + (vs + v)];
        KW[ch][pi][pj][k] = s;
    }
    if (t < 2) sb[t] = boff[t];
    __syncthreads();

    int idx = blockIdx.x * blockDim.x + t;
    int xq = idx & (W2 - 1);
    int y  = (idx >> 8) & (H2 - 1);
    int b  = idx >> 16;
    int pi = y & 1, pj = xq & 1;
    int hh = y >> 1, ww = xq >> 1;

    const float* m = g_mean + b * PLANE;

    float m3[9];
#pragma unroll
    for (int di = 0; di < 3; ++di)
#pragma unroll
        for (int dj = 0; dj < 3; ++dj) {
            int hn = hh - 1 + di, wn = ww - 1 + dj;
            m3[di * 3 + dj] = (hn >= 0 && hn < HH && wn >= 0 && wn < WW)
                              ? m[hn * WW + wn] : 0.f;
        }

    const float* kw0 = KW[0][pi][pj];
    const float* kw1 = KW[1][pi][pj];
    float a0 = 0.f, a1 = 0.f;
#pragma unroll
    for (int k = 0; k < 9; ++k) {
        a0 = fmaf(m3[k], kw0[k], a0);
        a1 = fmaf(m3[k], kw1[k], a1);
    }
    float s0 = (pj ? 0.25f : -0.25f) + 0.25f * fast_tanh(a0 + sb[0]);
    float s1 = (pi ? 0.25f : -0.25f) + 0.25f * fast_tanh(a1 + sb[1]);

    float mc = m3[4];
    float ev[9];
    float sum = 0.f;
#pragma unroll
    for (int k = 0; k < 9; ++k) {
        int di = k / 3 - 1;
        int dj = k % 3 - 1;
        float d  = m3[k] - mc;
        float e0 = s0 - (float)dj;
        float e1 = s1 - (float)di;
        float d2 = fmaf(e0, e0, fmaf(e1, e1, 0.2f));
        float kv = __fdividef(1.f, fmaf(d, d, 1.f) * d2);
        ev[k] = __expf(kv);
        sum += ev[k];
    }
    float inv = __fdividef(1.f, sum);
#pragma unroll
    for (int k = 0; k < 9; ++k)
        g_kern[((b * 9 + k) * H2 + y) * W2 + xq] = ev[k] * inv;
}

// ---------------------------------------------------------------------------
// Kernel C: CARAFE apply with DUPLICATED smem layout.
// x is stored in smem as (v,v) float2 pairs so every FFMA2 multiplicand is a
// single aligned LDS.64 — the 18 per-channel duplication MOVs vanish.
// Fill path: LDG.64 -> regs (one stage ahead) -> STS.128 (x,x,y,y).
// Block = (64-ch group, 2-input-row stripe, batch), 256 thr, 1 barrier/stage.
// ---------------------------------------------------------------------------
__global__ void __launch_bounds__(256, 4)
carafe_kernel(const float* __restrict__ x, float* __restrict__ out) {
    __shared__ __align__(16) float2 xs[NBUF][STAGE][CHP];

    int b  = blockIdx.z;
    int h0 = blockIdx.y * 2;
    int c0 = blockIdx.x * CPG;
    int t  = threadIdx.x;
    int r  = t >> 7;                  // 0..1 local input row (consumer)
    int w  = t & 127;                 // input column (consumer)
    int h  = h0 + r;

    // loader mapping: one float2 (2 cols) per thread per channel
    int lrow = t >> 6;                // 0..3  (input rows h0-1 .. h0+2)
    int lc2  = t & 63;                // float2 column index (cols 2*lc2, +1)
    int lok  = (h0 - 1 + lrow >= 0) && (h0 - 1 + lrow < HH);
    const float* xb = x + (size_t)b * CC * PLANE;
    const float2* lsrc0 = (const float2*)(xb + (size_t)(h0 - 1 + (lok ? lrow : 0)) * WW) + lc2;

    // hoist the 36 softmax weights for this 2x2 output cell (packed f32x2)
    const ull* kp = (const ull*)(g_kern + (size_t)b * 9 * H2 * W2);
    ull wk0[9], wk1[9];
#pragma unroll
    for (int k = 0; k < 9; ++k) {
        wk0[k] = kp[((size_t)k * H2 + 2 * h)     * (W2 / 2) + w];
        wk1[k] = kp[((size_t)k * H2 + 2 * h + 1) * (W2 / 2) + w];
    }

    // zero halo pair slots (col -1 -> pair idx 1, col 128 -> pair idx 130)
    if (t < NBUF * STAGE * 4 * 2) {
        int bufi = t >> 5, lt = t & 31;
        int ch = lt >> 3, rem = lt & 7, row = rem >> 1, side = rem & 1;
        xs[bufi][ch][row * PRSTR + (side ? 130 : 1)] = make_float2(0.f, 0.f);
    }

    uint32_t xs_base = (uint32_t)__cvta_generic_to_shared(&xs[0][0][0]);
    // STS address for this thread (within a channel tile), 16B aligned
    uint32_t sts_off = (uint32_t)(lrow * PRSTR + 2 + 2 * lc2) * 8u;
    // LDS base offset for consumer (pair index of col w-1 = w+1)
    uint32_t lds_off = (uint32_t)(r * PRSTR + (w + 1)) * 8u;

    // load one stage (STAGE channels) of float2 into registers
    float2 rg[STAGE];
    auto load_regs = [&](int s) {
#pragma unroll
        for (int ch = 0; ch < STAGE; ++ch) {
            float2 v = make_float2(0.f, 0.f);
            if (lok) v = lsrc0[(size_t)(c0 + s * STAGE + ch) * (PLANE / 2)];
            rg[ch] = v;
        }
    };
    // store regs duplicated into buffer buf
    auto sts_regs = [&](int buf) {
#pragma unroll
        for (int ch = 0; ch < STAGE; ++ch) {
            uint32_t a = xs_base + ((buf * STAGE + ch) * CHP) * 8u + sts_off;
            asm volatile("st.shared.v4.f32 [%0], {%1, %2, %3, %4};"
                         :: "r"(a), "f"(rg[ch].x), "f"(rg[ch].x),
                            "f"(rg[ch].y), "f"(rg[ch].y));
        }
    };

    // prologue
    load_regs(0);
    sts_regs(0);
    load_regs(1);
    __syncthreads();

#pragma unroll 1
    for (int s = 0; s < NS; ++s) {
        int buf = s & 1;
        int cbase = c0 + s * STAGE;

#pragma unroll
        for (int ch = 0; ch < STAGE; ++ch) {
            uint32_t abase = xs_base + ((buf * STAGE + ch) * CHP) * 8u + lds_off;
            ull acc0 = 0ull, acc1 = 0ull;
#pragma unroll
            for (int di = 0; di < 3; ++di) {
                uint32_t arow = abase + di * (PRSTR * 8u);
                ull v0, v1, v2;
                asm("ld.shared.b64 %0, [%1];"      : "=l"(v0) : "r"(arow));
                asm("ld.shared.b64 %0, [%1+8];"    : "=l"(v1) : "r"(arow));
                asm("ld.shared.b64 %0, [%1+16];"   : "=l"(v2) : "r"(arow));
                int k = di * 3;
                asm("fma.rn.f32x2 %0, %1, %2, %0;" : "+l"(acc0) : "l"(wk0[k+0]), "l"(v0));
                asm("fma.rn.f32x2 %0, %1, %2, %0;" : "+l"(acc1) : "l"(wk1[k+0]), "l"(v0));
                asm("fma.rn.f32x2 %0, %1, %2, %0;" : "+l"(acc0) : "l"(wk0[k+1]), "l"(v1));
                asm("fma.rn.f32x2 %0, %1, %2, %0;" : "+l"(acc1) : "l"(wk1[k+1]), "l"(v1));
                asm("fma.rn.f32x2 %0, %1, %2, %0;" : "+l"(acc0) : "l"(wk0[k+2]), "l"(v2));
                asm("fma.rn.f32x2 %0, %1, %2, %0;" : "+l"(acc1) : "l"(wk1[k+2]), "l"(v2));
            }
            float2* op = (float2*)(out + (((size_t)(b * CC + cbase + ch)) * H2
                                          + 2 * h) * W2);
            op[w] = *(float2*)&acc0;
            op[(W2 / 2) + w] = *(float2*)&acc1;
        }

        if (s + 1 < NS) {
            sts_regs(buf ^ 1);          // buf^1 last read in iter s-1 (pre-sync)
            if (s + 2 < NS) load_regs(s + 2);
        }
        __syncthreads();
    }
}

extern "C" void kernel_launch(void* const* d_in, const int* in_sizes, int n_in,
                              void* d_out, int out_size) {
    const float* x    = (const float*)d_in[0];
    const float* Woff = (const float*)d_in[1];
    const float* boff = (const float*)d_in[2];
    float* out = (float*)d_out;

    mean1_kernel<<<dim3(PLANE / 4 / 256, MG, BB), 256>>>(x);
    mean2_kernel<<<(BB * PLANE / 4) / 256, 256>>>();
    kern_kernel<<<(BB * H2 * W2) / 256, 256>>>(Woff, boff);
    carafe_kernel<<<dim3(CC / CPG, HH / 2, BB), 256>>>(x, out);
}

// round 8
// speedup vs baseline: 1.2282x; 1.2282x over previous
#include <cuda_runtime.h>
#include <cstdint>

#define BB 2
#define CC 256
#define HH 128
#define WW 128
#define H2 256
#define W2 256
#define PLANE (HH * WW)

#define CPG 32        // channels per carafe block (R3 measured-best config)
#define STAGE 4
#define NS (CPG / STAGE)
#define RSTR 132      // padded smem row stride (floats)
#define CHS (4 * RSTR + 4)

#define MG 16         // mean partial groups (interleaved innermost)

// scratch (no allocations allowed)
__device__ float g_part[BB * PLANE * MG];   // [b][pixel][group]
__device__ float g_kern[BB * 9 * H2 * W2];

typedef unsigned long long ull;

// ---------------------------------------------------------------------------
// cp.async helpers
// ---------------------------------------------------------------------------
__device__ __forceinline__ void cp_async16(uint32_t dst_smem, const void* src, int src_sz) {
    asm volatile("cp.async.cg.shared.global [%0], [%1], 16, %2;\n"
                 :: "r"(dst_smem), "l"(src), "r"(src_sz));
}
__device__ __forceinline__ void cp_commit() {
    asm volatile("cp.async.commit_group;\n");
}
template <int N>
__device__ __forceinline__ void cp_wait() {
    asm volatile("cp.async.wait_group %0;\n" :: "n"(N));
}

// ---------------------------------------------------------------------------
// Kernel A: partial channel sums, interleaved layout g_part[b][pixel][MG].
// Thread = one pixel for one 16-channel group. Reads coalesced (stride PLANE),
// write scattered at 64B stride (50% sector eff on 8.4MB - cheap).
// ---------------------------------------------------------------------------
__global__ void mean1_kernel(const float* __restrict__ x) {
    int t  = threadIdx.x;
    int p  = blockIdx.x * 256 + t;          // pixel [0, PLANE)
    int cg = blockIdx.y;                    // group [0, MG)
    int b  = blockIdx.z;
    const float* xp = x + (size_t)(b * CC + cg * (CC / MG)) * PLANE + p;
    float s = 0.f;
#pragma unroll
    for (int c = 0; c < CC / MG; ++c)
        s += xp[(size_t)c * PLANE];
    g_part[((size_t)b * PLANE + p) * MG + cg] = s;
}

// ---------------------------------------------------------------------------
// Kernel B (fused mean-combine + kernel-field):
// Block = 16x16 output tile. First 100 threads build the 10x10 mean tile
// (16 partials each via 4x LDG.128, L2-resident). Then per output pixel:
// parity-folded 3x3 conv (== 5x5 on nearest-up2) + offsets + gating + softmax.
// ---------------------------------------------------------------------------
__device__ __forceinline__ float fast_tanh(float x) {
    float e = __expf(2.0f * x);
    return __fdividef(e - 1.0f, e + 1.0f);
}

__global__ void __launch_bounds__(256)
kern_kernel(const float* __restrict__ Woff, const float* __restrict__ boff) {
    __shared__ float KW[2][2][2][9];   // [ch][pi][pj][di*3+dj]
    __shared__ float sb[2];
    __shared__ float sm[100];          // 10x10 mean tile

    int t  = threadIdx.x;
    int b  = blockIdx.z;
    int x0 = blockIdx.x * 16;
    int y0 = blockIdx.y * 16;

    if (t < 72) {
        int ch  = t / 36, rem = t % 36;
        int pi  = rem / 18, pj = (rem / 9) & 1, k = rem % 9;
        int di  = k / 3, dj = k % 3;
        int us  = pi == 0 ? di * 2 : (di == 0 ? 0 : di * 2 - 1);
        int uc  = pi == 0 ? (di < 2 ? 2 : 1) : (di == 0 ? 1 : 2);
        int vs  = pj == 0 ? dj * 2 : (dj == 0 ? 0 : dj * 2 - 1);
        int vc  = pj == 0 ? (dj < 2 ? 2 : 1) : (dj == 0 ? 1 : 2);
        float s = 0.f;
        for (int u = 0; u < uc; ++u)
            for (int v = 0; v < vc; ++v)
                s += Woff[ch * 25 + (us + u) * 5 + (vs + v)];
        KW[ch][pi][pj][k] = s;
    } else if (t < 74) {
        sb[t - 72] = boff[t - 72];
    }

    // 10x10 mean tile: input rows hh0..hh0+9, cols ww0..ww0+9
    int hh0 = (y0 >> 1) - 1;
    int ww0 = (x0 >> 1) - 1;
    if (t < 100) {
        int hn = hh0 + t / 10;
        int wn = ww0 + t % 10;
        float s = 0.f;
        if (hn >= 0 && hn < HH && wn >= 0 && wn < WW) {
            const float4* pp = (const float4*)
                (g_part + ((size_t)b * PLANE + hn * WW + wn) * MG);
            float4 v0 = pp[0], v1 = pp[1], v2 = pp[2], v3 = pp[3];
            s = ((v0.x + v0.y) + (v0.z + v0.w)) + ((v1.x + v1.y) + (v1.z + v1.w))
              + ((v2.x + v2.y) + (v2.z + v2.w)) + ((v3.x + v3.y) + (v3.z + v3.w));
            s *= (1.0f / CC);
        }
        sm[t] = s;
    }
    __syncthreads();

    int tx = t & 15, ty = t >> 4;
    int xq = x0 + tx, y = y0 + ty;
    int pi = y & 1, pj = xq & 1;
    int lh = (ty >> 1) + 1;            // local input row in sm (1..8)
    int lw = (tx >> 1) + 1;

    float m3[9];
#pragma unroll
    for (int di = 0; di < 3; ++di)
#pragma unroll
        for (int dj = 0; dj < 3; ++dj)
            m3[di * 3 + dj] = sm[(lh - 1 + di) * 10 + (lw - 1 + dj)];

    const float* kw0 = KW[0][pi][pj];
    const float* kw1 = KW[1][pi][pj];
    float a0 = 0.f, a1 = 0.f;
#pragma unroll
    for (int k = 0; k < 9; ++k) {
        a0 = fmaf(m3[k], kw0[k], a0);
        a1 = fmaf(m3[k], kw1[k], a1);
    }
    float s0 = (pj ? 0.25f : -0.25f) + 0.25f * fast_tanh(a0 + sb[0]);
    float s1 = (pi ? 0.25f : -0.25f) + 0.25f * fast_tanh(a1 + sb[1]);

    float mc = m3[4];
    float ev[9];
    float sum = 0.f;
#pragma unroll
    for (int k = 0; k < 9; ++k) {
        int di = k / 3 - 1;
        int dj = k % 3 - 1;
        float d  = m3[k] - mc;
        float e0 = s0 - (float)dj;
        float e1 = s1 - (float)di;
        float d2 = fmaf(e0, e0, fmaf(e1, e1, 0.2f));
        float kv = __fdividef(1.f, fmaf(d, d, 1.f) * d2);
        ev[k] = __expf(kv);
        sum += ev[k];
    }
    float inv = __fdividef(1.f, sum);
#pragma unroll
    for (int k = 0; k < 9; ++k)
        g_kern[((b * 9 + k) * H2 + y) * W2 + xq] = ev[k] * inv;
}

// ---------------------------------------------------------------------------
// Kernel C: CARAFE apply (R3 measured-best configuration, verbatim).
// Block = (32-channel group, 2-input-row stripe, batch). 256 threads.
// Thread = one input pixel -> 2x2 output cell; 36 weights in regs (f32x2);
// x planes streamed via cp.async double buffer; packed f32x2 FFMA.
// ---------------------------------------------------------------------------
__global__ void __launch_bounds__(256, 4)
carafe_kernel(const float* __restrict__ x, float* __restrict__ out) {
    __shared__ __align__(16) float xs[2][STAGE][CHS];

    int b  = blockIdx.z;
    int h0 = blockIdx.y * 2;
    int c0 = blockIdx.x * CPG;
    int t  = threadIdx.x;
    int r  = t >> 7;
    int w  = t & 127;
    int h  = h0 + r;

    const ull* kp = (const ull*)(g_kern + (size_t)b * 9 * H2 * W2);
    ull wk0[9], wk1[9];
#pragma unroll
    for (int k = 0; k < 9; ++k) {
        wk0[k] = kp[((size_t)k * H2 + 2 * h)     * (W2 / 2) + w];
        wk1[k] = kp[((size_t)k * H2 + 2 * h + 1) * (W2 / 2) + w];
    }

    if (t < 64) {
        int bufi = t >> 5, lt = t & 31;
        int ch = lt >> 3, rem = lt & 7, row = rem >> 1, side = rem & 1;
        xs[bufi][ch][row * RSTR + (side ? RSTR : 3)] = 0.f;
    }

    const float* xb = x + (size_t)b * CC * PLANE;

    auto load_stage = [&](int s, int buf) {
        int cb = c0 + s * STAGE;
#pragma unroll
        for (int u = 0; u < 2; ++u) {
            int lin  = u * 256 + t;
            int ch   = lin >> 7;
            int rem  = lin & 127;
            int row  = rem >> 5;
            int col4 = rem & 31;
            int grow = h0 - 1 + row;
            int ok   = (grow >= 0 && grow < HH);
            const float* src = xb + (size_t)(cb + ch) * PLANE
                             + (ok ? grow : 0) * WW + (col4 << 2);
            uint32_t dst = (uint32_t)__cvta_generic_to_shared(
                &xs[buf][ch][row * RSTR + 4 + (col4 << 2)]);
            cp_async16(dst, src, ok ? 16 : 0);
        }
    };

    load_stage(0, 0);
    cp_commit();

#pragma unroll 1
    for (int s = 0; s < NS; ++s) {
        int buf = s & 1;
        __syncthreads();
        if (s + 1 < NS) { load_stage(s + 1, buf ^ 1); cp_commit(); cp_wait<1>(); }
        else           { cp_wait<0>(); }
        __syncthreads();

        int cbase = c0 + s * STAGE;
#pragma unroll
        for (int ch = 0; ch < STAGE; ++ch) {
            const float* base = &xs[buf][ch][r * RSTR + 4 + w];
            ull acc0 = 0ull, acc1 = 0ull;
#pragma unroll
            for (int di = 0; di < 3; ++di) {
                const float* rp = base + di * RSTR;
                float xv[3] = { rp[-1], rp[0], rp[1] };
#pragma unroll
                for (int dj = 0; dj < 3; ++dj) {
                    int k = di * 3 + dj;
                    unsigned vu = __float_as_uint(xv[dj]);
                    ull vv;
                    asm("mov.b64 %0, {%1, %2};" : "=l"(vv) : "r"(vu), "r"(vu));
                    asm("fma.rn.f32x2 %0, %1, %2, %0;"
                        : "+l"(acc0) : "l"(wk0[k]), "l"(vv));
                    asm("fma.rn.f32x2 %0, %1, %2, %0;"
                        : "+l"(acc1) : "l"(wk1[k]), "l"(vv));
                }
            }
            float2* op = (float2*)(out + (((size_t)(b * CC + cbase + ch)) * H2
                                          + 2 * h) * W2);
            op[w] = *(float2*)&acc0;
            op[(W2 / 2) + w] = *(float2*)&acc1;
        }
    }
}

extern "C" void kernel_launch(void* const* d_in, const int* in_sizes, int n_in,
                              void* d_out, int out_size) {
    const float* x    = (const float*)d_in[0];
    const float* Woff = (const float*)d_in[1];
    const float* boff = (const float*)d_in[2];
    float* out = (float*)d_out;

    mean1_kernel<<<dim3(PLANE / 256, MG, BB), 256>>>(x);
    kern_kernel<<<dim3(W2 / 16, H2 / 16, BB), 256>>>(Woff, boff);
    carafe_kernel<<<dim3(CC / CPG, HH / 2, BB), 256>>>(x, out);
}

// round 9
// speedup vs baseline: 1.2474x; 1.0156x over previous
#include <cuda_runtime.h>
#include <cstdint>

#define BB 2
#define CC 256
#define HH 128
#define WW 128
#define H2 256
#define W2 256
#define PLANE (HH * WW)

#define CPG 32        // channels per carafe block (R3 measured-best config)
#define STAGE 4
#define NS (CPG / STAGE)
#define RSTR 132      // padded smem row stride (floats)
#define CHS (4 * RSTR + 4)

#define MG 16         // mean partial groups (planar layout)

// scratch (no allocations allowed)
__device__ float g_part[BB * MG * PLANE];   // [b][group][pixel]  (planar)
__device__ float g_kern[BB * 9 * H2 * W2];

typedef unsigned long long ull;

// ---------------------------------------------------------------------------
// cp.async helpers
// ---------------------------------------------------------------------------
__device__ __forceinline__ void cp_async16(uint32_t dst_smem, const void* src, int src_sz) {
    asm volatile("cp.async.cg.shared.global [%0], [%1], 16, %2;\n"
                 :: "r"(dst_smem), "l"(src), "r"(src_sz));
}
__device__ __forceinline__ void cp_commit() {
    asm volatile("cp.async.commit_group;\n");
}
template <int N>
__device__ __forceinline__ void cp_wait() {
    asm volatile("cp.async.wait_group %0;\n" :: "n"(N));
}

// ---------------------------------------------------------------------------
// Kernel A: partial channel sums, PLANAR layout g_part[b][group][pixel].
// float4 reads (16 channels, stride PLANE) and float4 coalesced writes.
// ---------------------------------------------------------------------------
__global__ void mean1_kernel(const float* __restrict__ x) {
    int t  = threadIdx.x;
    int p4 = blockIdx.x * 256 + t;          // float4-pixel [0, PLANE/4)
    int cg = blockIdx.y;                    // group [0, MG)
    int b  = blockIdx.z;
    const float4* xp = (const float4*)x
                     + (size_t)(b * CC + cg * (CC / MG)) * (PLANE / 4) + p4;
    float4 s = make_float4(0.f, 0.f, 0.f, 0.f);
#pragma unroll
    for (int c = 0; c < CC / MG; ++c) {
        float4 v = xp[(size_t)c * (PLANE / 4)];
        s.x += v.x; s.y += v.y; s.z += v.z; s.w += v.w;
    }
    ((float4*)g_part)[((size_t)(b * MG + cg)) * (PLANE / 4) + p4] = s;
}

// ---------------------------------------------------------------------------
// Kernel B (fused 16-way mean-combine + kernel-field):
// Block = 16x16 output tile. First 100 threads build the 10x10 mean tile
// (16 planar partials each; scattered but L2-resident). Then per output
// pixel: parity-folded 3x3 conv (== 5x5 on nearest-up2) + offsets + gating
// + softmax.
// ---------------------------------------------------------------------------
__device__ __forceinline__ float fast_tanh(float x) {
    float e = __expf(2.0f * x);
    return __fdividef(e - 1.0f, e + 1.0f);
}

__global__ void __launch_bounds__(256)
kern_kernel(const float* __restrict__ Woff, const float* __restrict__ boff) {
    __shared__ float KW[2][2][2][9];   // [ch][pi][pj][di*3+dj]
    __shared__ float sb[2];
    __shared__ float sm[100];          // 10x10 mean tile

    int t  = threadIdx.x;
    int b  = blockIdx.z;
    int x0 = blockIdx.x * 16;
    int y0 = blockIdx.y * 16;

    if (t < 72) {
        int ch  = t / 36, rem = t % 36;
        int pi  = rem / 18, pj = (rem / 9) & 1, k = rem % 9;
        int di  = k / 3, dj = k % 3;
        int us  = pi == 0 ? di * 2 : (di == 0 ? 0 : di * 2 - 1);
        int uc  = pi == 0 ? (di < 2 ? 2 : 1) : (di == 0 ? 1 : 2);
        int vs  = pj == 0 ? dj * 2 : (dj == 0 ? 0 : dj * 2 - 1);
        int vc  = pj == 0 ? (dj < 2 ? 2 : 1) : (dj == 0 ? 1 : 2);
        float s = 0.f;
        for (int u = 0; u < uc; ++u)
            for (int v = 0; v < vc; ++v)
                s += Woff[ch * 25 + (us + u) * 5 + (vs + v)];
        KW[ch][pi][pj][k] = s;
    } else if (t < 74) {
        sb[t - 72] = boff[t - 72];
    }

    // 10x10 mean tile: input rows hh0..hh0+9, cols ww0..ww0+9
    int hh0 = (y0 >> 1) - 1;
    int ww0 = (x0 >> 1) - 1;
    if (t < 100) {
        int hn = hh0 + t / 10;
        int wn = ww0 + t % 10;
        float s = 0.f;
        if (hn >= 0 && hn < HH && wn >= 0 && wn < WW) {
            const float* pp = g_part + (size_t)b * MG * PLANE + hn * WW + wn;
            float acc[4] = {0.f, 0.f, 0.f, 0.f};
#pragma unroll
            for (int g = 0; g < MG; ++g)
                acc[g & 3] += pp[(size_t)g * PLANE];
            s = ((acc[0] + acc[1]) + (acc[2] + acc[3])) * (1.0f / CC);
        }
        sm[t] = s;
    }
    __syncthreads();

    int tx = t & 15, ty = t >> 4;
    int xq = x0 + tx, y = y0 + ty;
    int pi = y & 1, pj = xq & 1;
    int lh = (ty >> 1) + 1;
    int lw = (tx >> 1) + 1;

    float m3[9];
#pragma unroll
    for (int di = 0; di < 3; ++di)
#pragma unroll
        for (int dj = 0; dj < 3; ++dj)
            m3[di * 3 + dj] = sm[(lh - 1 + di) * 10 + (lw - 1 + dj)];

    const float* kw0 = KW[0][pi][pj];
    const float* kw1 = KW[1][pi][pj];
    float a0 = 0.f, a1 = 0.f;
#pragma unroll
    for (int k = 0; k < 9; ++k) {
        a0 = fmaf(m3[k], kw0[k], a0);
        a1 = fmaf(m3[k], kw1[k], a1);
    }
    float s0 = (pj ? 0.25f : -0.25f) + 0.25f * fast_tanh(a0 + sb[0]);
    float s1 = (pi ? 0.25f : -0.25f) + 0.25f * fast_tanh(a1 + sb[1]);

    float mc = m3[4];
    float ev[9];
    float sum = 0.f;
#pragma unroll
    for (int k = 0; k < 9; ++k) {
        int di = k / 3 - 1;
        int dj = k % 3 - 1;
        float d  = m3[k] - mc;
        float e0 = s0 - (float)dj;
        float e1 = s1 - (float)di;
        float d2 = fmaf(e0, e0, fmaf(e1, e1, 0.2f));
        float kv = __fdividef(1.f, fmaf(d, d, 1.f) * d2);
        ev[k] = __expf(kv);
        sum += ev[k];
    }
    float inv = __fdividef(1.f, sum);
#pragma unroll
    for (int k = 0; k < 9; ++k)
        g_kern[((b * 9 + k) * H2 + y) * W2 + xq] = ev[k] * inv;
}

// ---------------------------------------------------------------------------
// Kernel C: CARAFE apply (R3 measured-best configuration, verbatim).
// ---------------------------------------------------------------------------
__global__ void __launch_bounds__(256, 4)
carafe_kernel(const float* __restrict__ x, float* __restrict__ out) {
    __shared__ __align__(16) float xs[2][STAGE][CHS];

    int b  = blockIdx.z;
    int h0 = blockIdx.y * 2;
    int c0 = blockIdx.x * CPG;
    int t  = threadIdx.x;
    int r  = t >> 7;
    int w  = t & 127;
    int h  = h0 + r;

    const ull* kp = (const ull*)(g_kern + (size_t)b * 9 * H2 * W2);
    ull wk0[9], wk1[9];
#pragma unroll
    for (int k = 0; k < 9; ++k) {
        wk0[k] = kp[((size_t)k * H2 + 2 * h)     * (W2 / 2) + w];
        wk1[k] = kp[((size_t)k * H2 + 2 * h + 1) * (W2 / 2) + w];
    }

    if (t < 64) {
        int bufi = t >> 5, lt = t & 31;
        int ch = lt >> 3, rem = lt & 7, row = rem >> 1, side = rem & 1;
        xs[bufi][ch][row * RSTR + (side ? RSTR : 3)] = 0.f;
    }

    const float* xb = x + (size_t)b * CC * PLANE;

    auto load_stage = [&](int s, int buf) {
        int cb = c0 + s * STAGE;
#pragma unroll
        for (int u = 0; u < 2; ++u) {
            int lin  = u * 256 + t;
            int ch   = lin >> 7;
            int rem  = lin & 127;
            int row  = rem >> 5;
            int col4 = rem & 31;
            int grow = h0 - 1 + row;
            int ok   = (grow >= 0 && grow < HH);
            const float* src = xb + (size_t)(cb + ch) * PLANE
                             + (ok ? grow : 0) * WW + (col4 << 2);
            uint32_t dst = (uint32_t)__cvta_generic_to_shared(
                &xs[buf][ch][row * RSTR + 4 + (col4 << 2)]);
            cp_async16(dst, src, ok ? 16 : 0);
        }
    };

    load_stage(0, 0);
    cp_commit();

#pragma unroll 1
    for (int s = 0; s < NS; ++s) {
        int buf = s & 1;
        __syncthreads();
        if (s + 1 < NS) { load_stage(s + 1, buf ^ 1); cp_commit(); cp_wait<1>(); }
        else           { cp_wait<0>(); }
        __syncthreads();

        int cbase = c0 + s * STAGE;
#pragma unroll
        for (int ch = 0; ch < STAGE; ++ch) {
            const float* base = &xs[buf][ch][r * RSTR + 4 + w];
            ull acc0 = 0ull, acc1 = 0ull;
#pragma unroll
            for (int di = 0; di < 3; ++di) {
                const float* rp = base + di * RSTR;
                float xv[3] = { rp[-1], rp[0], rp[1] };
#pragma unroll
                for (int dj = 0; dj < 3; ++dj) {
                    int k = di * 3 + dj;
                    unsigned vu = __float_as_uint(xv[dj]);
                    ull vv;
                    asm("mov.b64 %0, {%1, %2};" : "=l"(vv) : "r"(vu), "r"(vu));
                    asm("fma.rn.f32x2 %0, %1, %2, %0;"
                        : "+l"(acc0) : "l"(wk0[k]), "l"(vv));
                    asm("fma.rn.f32x2 %0, %1, %2, %0;"
                        : "+l"(acc1) : "l"(wk1[k]), "l"(vv));
                }
            }
            float2* op = (float2*)(out + (((size_t)(b * CC + cbase + ch)) * H2
                                          + 2 * h) * W2);
            op[w] = *(float2*)&acc0;
            op[(W2 / 2) + w] = *(float2*)&acc1;
        }
    }
}

extern "C" void kernel_launch(void* const* d_in, const int* in_sizes, int n_in,
                              void* d_out, int out_size) {
    const float* x    = (const float*)d_in[0];
    const float* Woff = (const float*)d_in[1];
    const float* boff = (const float*)d_in[2];
    float* out = (float*)d_out;

    mean1_kernel<<<dim3(PLANE / 4 / 256, MG, BB), 256>>>(x);
    kern_kernel<<<dim3(W2 / 16, H2 / 16, BB), 256>>>(Woff, boff);
    carafe_kernel<<<dim3(CC / CPG, HH / 2, BB), 256>>>(x, out);
}